// round 5
// baseline (speedup 1.0000x reference)
#include <cuda_runtime.h>
#include <cuda_bf16.h>
#include <cstdint>

#define NN 40000
#define NP 40064   // 313 * 128, padded row count
#define NE 320000
#define NG 64
#define IND 128
#define H4 256
#define OUTD 128
#define CAT 512

// ---------------- scratch (device globals; no allocation allowed) ----------------
__device__ int   g_outcnt[NN];
__device__ int   g_incnt[NN];
__device__ int   g_cursor[NN];
__device__ int   g_rowptr[NN + 1];
__device__ int   g_bsum[64];
__device__ float g_outinv[NN];
__device__ float g_ininv[NN];
__device__ int   g_es[NE];
__device__ float g_ec[NE];
__device__ float g_f1[NP * H4];
__device__ float g_y2[NP * H4];
__device__ float g_y3[NP * OUTD];
__device__ float g_readout[NG * OUTD];
// split-bf16 activation planes (A operands of GEMMs), padded to NP rows
__device__ __nv_bfloat16 g_xh[NP * IND],  g_xl[NP * IND];
__device__ __nv_bfloat16 g_a1h[NP * IND], g_a1l[NP * IND];
__device__ __nv_bfloat16 g_ch[NP * CAT],  g_cl[NP * CAT];
__device__ __nv_bfloat16 g_x2h[NP * H4],  g_x2l[NP * H4];
// weights pre-split to bf16 hi/lo, transposed to [N][K]
// layout: W1 @0 (32768), fc1 @32768 (32768), W2 @65536 (131072), W3 @196608 (32768)
__device__ __nv_bfloat16 g_bh[229376];
__device__ __nv_bfloat16 g_bl[229376];

// ---------------- helpers ----------------
__device__ __forceinline__ uint32_t smem_u32(const void* p) {
    uint32_t a;
    asm("{ .reg .u64 t; cvta.to.shared.u64 t, %1; cvt.u32.u64 %0, t; }" : "=r"(a) : "l"(p));
    return a;
}
__device__ __forceinline__ void cpa16(uint32_t dst, const void* src) {
    asm volatile("cp.async.cg.shared.global [%0], [%1], 16;" :: "r"(dst), "l"(src) : "memory");
}
__device__ __forceinline__ void cpa_commit() {
    asm volatile("cp.async.commit_group;" ::: "memory");
}
__device__ __forceinline__ void cpa_wait0() {
    asm volatile("cp.async.wait_group 0;" ::: "memory");
}
#define MMA16816(d, a, b)                                                     \
    asm volatile(                                                             \
        "mma.sync.aligned.m16n8k16.row.col.f32.bf16.bf16.f32 "                \
        "{%0,%1,%2,%3}, {%4,%5,%6,%7}, {%8,%9}, {%0,%1,%2,%3};"               \
        : "+f"((d)[0]), "+f"((d)[1]), "+f"((d)[2]), "+f"((d)[3])              \
        : "r"((a)[0]), "r"((a)[1]), "r"((a)[2]), "r"((a)[3]),                 \
          "r"((b)[0]), "r"((b)[1]))
#define LDSM4(R, addr)                                                        \
    asm volatile("ldmatrix.sync.aligned.m8n8.x4.shared.b16 {%0,%1,%2,%3}, [%4];" \
        : "=r"((R)[0]), "=r"((R)[1]), "=r"((R)[2]), "=r"((R)[3]) : "r"(addr))

__device__ __forceinline__ void split1(float v, __nv_bfloat16& h, __nv_bfloat16& l) {
    h = __float2bfloat16(v);
    l = __float2bfloat16(v - __bfloat162float(h));
}
__device__ __forceinline__ void split4(const float4 v, uint32_t* h2, uint32_t* l2) {
    __nv_bfloat16 hx, lx, hy, ly, hz, lz, hw, lw;
    split1(v.x, hx, lx); split1(v.y, hy, ly);
    split1(v.z, hz, lz); split1(v.w, hw, lw);
    __nv_bfloat162 a = __halves2bfloat162(hx, hy), b = __halves2bfloat162(hz, hw);
    __nv_bfloat162 c = __halves2bfloat162(lx, ly), d = __halves2bfloat162(lz, lw);
    h2[0] = *(uint32_t*)&a; h2[1] = *(uint32_t*)&b;
    l2[0] = *(uint32_t*)&c; l2[1] = *(uint32_t*)&d;
}

// ---------------- setup kernels ----------------
__global__ void k_zero() {
    int i = blockIdx.x * blockDim.x + threadIdx.x;
    if (i < NN) { g_outcnt[i] = 0; g_incnt[i] = 0; g_cursor[i] = 0; }
    if (i < NG * OUTD) g_readout[i] = 0.f;
}

__global__ void k_deg(const int* __restrict__ src, const int* __restrict__ dst) {
    int e = blockIdx.x * blockDim.x + threadIdx.x;
    if (e < NE) {
        atomicAdd(&g_outcnt[src[e]], 1);
        atomicAdd(&g_incnt[dst[e]], 1);
    }
}

// per-block scan (+ merged inv computation)
__global__ void k_scan_a() {
    __shared__ int sh[1024];
    int b = blockIdx.x, t = threadIdx.x;
    int idx = b * 1024 + t;
    int v = (idx < NN) ? g_incnt[idx] : 0;
    if (idx < NN) {
        g_ininv[idx]  = rsqrtf((float)max(v, 1));
        g_outinv[idx] = rsqrtf((float)max(g_outcnt[idx], 1));
    }
    sh[t] = v;
    __syncthreads();
#pragma unroll
    for (int off = 1; off < 1024; off <<= 1) {
        int u = (t >= off) ? sh[t - off] : 0;
        __syncthreads();
        sh[t] += u;
        __syncthreads();
    }
    int incl = sh[t];
    if (idx <= NN) g_rowptr[idx] = incl - v;
    if (t == 1023) g_bsum[b] = incl;
}
__global__ void k_scan_b() {
    if (threadIdx.x == 0) {
        int s = 0;
        for (int i = 0; i < 40; i++) { int v = g_bsum[i]; g_bsum[i] = s; s += v; }
    }
}
__global__ void k_scan_c() {
    int idx = blockIdx.x * blockDim.x + threadIdx.x;
    if (idx <= NN) g_rowptr[idx] += g_bsum[idx >> 10];
}

__global__ void k_place(const int* __restrict__ src, const int* __restrict__ dst,
                        const float* __restrict__ w) {
    int e = blockIdx.x * blockDim.x + threadIdx.x;
    if (e >= NE) return;
    float4 ww = *(const float4*)(w + 4 * e);
    float m = fmaxf(fmaxf(ww.x, ww.y), fmaxf(ww.z, ww.w));
    int d = dst[e];
    int s = src[e];
    int pos = g_rowptr[d] + atomicAdd(&g_cursor[d], 1);
    g_es[pos] = s;
    g_ec[pos] = m * g_outinv[s];
}

// all 4 weights: fp32 [K][N] -> bf16 hi/lo [N][K], one kernel
__global__ void k_convB_all(const float* __restrict__ W1, const float* __restrict__ F1,
                            const float* __restrict__ W2, const float* __restrict__ W3) {
    int idx = blockIdx.x * blockDim.x + threadIdx.x;
    if (idx >= 229376) return;
    const float* W; int K, N, base;
    if (idx < 32768)       { W = W1; K = 128; N = 256; base = 0; }
    else if (idx < 65536)  { W = F1; K = 128; N = 256; base = 32768; }
    else if (idx < 196608) { W = W2; K = 512; N = 256; base = 65536; }
    else                   { W = W3; K = 256; N = 128; base = 196608; }
    int li = idx - base;
    int k = li % K, n = li / K;
    float v = W[k * N + n];
    __nv_bfloat16 h, l;
    split1(v, h, l);
    g_bh[idx] = h;
    g_bl[idx] = l;
}

// x -> split planes (pads zeroed)
__global__ void k_convA(const float* __restrict__ x) {
    int idx = blockIdx.x * blockDim.x + threadIdx.x;
    if (idx >= NP * IND) return;
    float v = (idx < NN * IND) ? x[idx] : 0.f;
    __nv_bfloat16 h, l;
    split1(v, h, l);
    g_xh[idx] = h;
    g_xl[idx] = l;
}

// ---------------- aggregation: one warp per dst node ----------------
// MODE 0: split-bf16 out (no relu); MODE 1: relu + split out; MODE 2: relu + readout atomics
template <int D, int MODE>
__global__ void k_agg(const float* __restrict__ in, __nv_bfloat16* __restrict__ oh,
                      __nv_bfloat16* __restrict__ ol, const int* __restrict__ gid) {
    int warp = (blockIdx.x * blockDim.x + threadIdx.x) >> 5;
    int lane = threadIdx.x & 31;
    if (warp >= NP) return;
    constexpr int V = D / 128;
    if (warp >= NN) {  // pad rows: zero planes
        if (MODE != 2) {
            uint32_t* ph = (uint32_t*)(oh + (size_t)warp * D);
            uint32_t* pl = (uint32_t*)(ol + (size_t)warp * D);
#pragma unroll
            for (int v = 0; v < V; v++) {
                ph[v * 64 + lane * 2] = 0; ph[v * 64 + lane * 2 + 1] = 0;
                pl[v * 64 + lane * 2] = 0; pl[v * 64 + lane * 2 + 1] = 0;
            }
        }
        return;
    }
    int beg = g_rowptr[warp];
    int end = g_rowptr[warp + 1];
    float4 acc[V];
#pragma unroll
    for (int v = 0; v < V; v++) acc[v] = make_float4(0.f, 0.f, 0.f, 0.f);
    for (int e = beg; e < end; e++) {
        int s = g_es[e];
        float c = g_ec[e];
        const float4* p = (const float4*)(in + (size_t)s * D) + lane;
#pragma unroll
        for (int v = 0; v < V; v++) {
            float4 t = p[v * 32];
            acc[v].x = fmaf(c, t.x, acc[v].x);
            acc[v].y = fmaf(c, t.y, acc[v].y);
            acc[v].z = fmaf(c, t.z, acc[v].z);
            acc[v].w = fmaf(c, t.w, acc[v].w);
        }
    }
    float inv = g_ininv[warp];
#pragma unroll
    for (int v = 0; v < V; v++) {
        acc[v].x *= inv; acc[v].y *= inv; acc[v].z *= inv; acc[v].w *= inv;
        if (MODE >= 1) {
            acc[v].x = fmaxf(acc[v].x, 0.f);
            acc[v].y = fmaxf(acc[v].y, 0.f);
            acc[v].z = fmaxf(acc[v].z, 0.f);
            acc[v].w = fmaxf(acc[v].w, 0.f);
        }
    }
    if (MODE == 2) {
        int g = gid[warp];
        float* r = g_readout + g * OUTD + lane * 4;
        atomicAdd(r + 0, acc[0].x);
        atomicAdd(r + 1, acc[0].y);
        atomicAdd(r + 2, acc[0].z);
        atomicAdd(r + 3, acc[0].w);
    } else {
        uint32_t* ph = (uint32_t*)(oh + (size_t)warp * D);
        uint32_t* pl = (uint32_t*)(ol + (size_t)warp * D);
#pragma unroll
        for (int v = 0; v < V; v++) {
            uint32_t h2[2], l2[2];
            split4(acc[v], h2, l2);
            ph[v * 64 + lane * 2] = h2[0]; ph[v * 64 + lane * 2 + 1] = h2[1];
            pl[v * 64 + lane * 2] = l2[0]; pl[v * 64 + lane * 2 + 1] = l2[1];
        }
    }
}

// ---------------- split-bf16 mma.sync GEMM, ldmatrix + cp.async ----------------
// C[M,N] = (Ah+Al)@(Bh+Bl) approx = Ah*Bh + Ah*Bl + Al*Bh, fp32 accum.
// Block tile 128x128, BK=32 fp32 per stage, 2-stage cp.async pipeline.
// smem rows padded to 80B -> conflict-free ldmatrix.
// EPI: 0 = raw fp32 out, 1 = relu + split-bf16 out
template <int K, int EPI>
__global__ __launch_bounds__(256, 2) void k_mma(
    const __nv_bfloat16* __restrict__ Ah, const __nv_bfloat16* __restrict__ Al,
    const __nv_bfloat16* __restrict__ Bh, const __nv_bfloat16* __restrict__ Bl,
    float* __restrict__ C, __nv_bfloat16* __restrict__ Ch, __nv_bfloat16* __restrict__ Cl,
    int ldC, int colOff) {
    extern __shared__ __align__(16) uint8_t smem[];
    constexpr int NC = K / 32;
    constexpr uint32_t AH_ = 0, AL_ = 10240, BH_ = 20480, BL_ = 30720, STG = 40960;
    const int tid = threadIdx.x;
    const int wid = tid >> 5, lane = tid & 31;
    const int wm = wid & 3, wn = wid >> 2;
    const int m0 = blockIdx.x * 128;
    const int nblk = blockIdx.y * 128;
    const uint32_t sb = smem_u32(smem);

    float acc[2][8][4];
#pragma unroll
    for (int mi = 0; mi < 2; mi++)
#pragma unroll
        for (int ni = 0; ni < 8; ni++)
#pragma unroll
            for (int r = 0; r < 4; r++) acc[mi][ni][r] = 0.f;

    // loaders: thread -> (row 0..127, plane hi/lo), 64B A + 64B B per stage
    const int lrow = tid & 127, lpl = tid >> 7;
    const __nv_bfloat16* aS = (lpl ? Al : Ah) + (size_t)(m0 + lrow) * K;
    const __nv_bfloat16* bS = (lpl ? Bl : Bh) + (size_t)(nblk + lrow) * K;
    const uint32_t aD = (lpl ? AL_ : AH_) + (uint32_t)lrow * 80;
    const uint32_t bD = (lpl ? BL_ : BH_) + (uint32_t)lrow * 80;

    // fragment base offsets (ldmatrix thread mapping)
    const uint32_t aoff = AH_ + (uint32_t)(wm * 32 + (lane & 7) + ((lane >> 3) & 1) * 8) * 80 +
                          (lane >> 4) * 16;
    const uint32_t boff = BH_ + (uint32_t)(wn * 64 + ((lane >> 4) & 1) * 8 + (lane & 7)) * 80 +
                          ((lane >> 3) & 1) * 16;

    // prologue: stage 0
    {
        uint32_t st = sb;
#pragma unroll
        for (int j = 0; j < 4; j++) cpa16(st + aD + j * 16, aS + j * 8);
#pragma unroll
        for (int j = 0; j < 4; j++) cpa16(st + bD + j * 16, bS + j * 8);
        cpa_commit();
    }

    for (int c = 0; c < NC; c++) {
        cpa_wait0();
        __syncthreads();
        if (c + 1 < NC) {
            uint32_t st = sb + ((c + 1) & 1) * STG;
            const __nv_bfloat16* ap = aS + (c + 1) * 32;
            const __nv_bfloat16* bp = bS + (c + 1) * 32;
#pragma unroll
            for (int j = 0; j < 4; j++) cpa16(st + aD + j * 16, ap + j * 8);
#pragma unroll
            for (int j = 0; j < 4; j++) cpa16(st + bD + j * 16, bp + j * 8);
            cpa_commit();
        }
        uint32_t st = sb + (c & 1) * STG;
#pragma unroll
        for (int kk = 0; kk < 2; kk++) {
            const uint32_t ko = kk * 32;
            uint32_t afH[2][4], afL[2][4], bf[8][2];
#pragma unroll
            for (int mi = 0; mi < 2; mi++) {
                LDSM4(afH[mi], st + aoff + mi * 1280 + ko);
                LDSM4(afL[mi], st + aoff + (AL_ - AH_) + mi * 1280 + ko);
            }
#pragma unroll
            for (int p = 0; p < 4; p++) {
                uint32_t r4[4];
                LDSM4(r4, st + boff + p * 1280 + ko);
                bf[2 * p][0] = r4[0]; bf[2 * p][1] = r4[1];
                bf[2 * p + 1][0] = r4[2]; bf[2 * p + 1][1] = r4[3];
            }
#pragma unroll
            for (int mi = 0; mi < 2; mi++)
#pragma unroll
                for (int ni = 0; ni < 8; ni++) MMA16816(acc[mi][ni], afH[mi], bf[ni]);
#pragma unroll
            for (int mi = 0; mi < 2; mi++)
#pragma unroll
                for (int ni = 0; ni < 8; ni++) MMA16816(acc[mi][ni], afL[mi], bf[ni]);
#pragma unroll
            for (int p = 0; p < 4; p++) {
                uint32_t r4[4];
                LDSM4(r4, st + boff + (BL_ - BH_) + p * 1280 + ko);
                bf[2 * p][0] = r4[0]; bf[2 * p][1] = r4[1];
                bf[2 * p + 1][0] = r4[2]; bf[2 * p + 1][1] = r4[3];
            }
#pragma unroll
            for (int mi = 0; mi < 2; mi++)
#pragma unroll
                for (int ni = 0; ni < 8; ni++) MMA16816(acc[mi][ni], afH[mi], bf[ni]);
        }
        __syncthreads();
    }

    // epilogue (buffers NP-padded: no row guards)
    const int g = lane >> 2, q = lane & 3;
#pragma unroll
    for (int mi = 0; mi < 2; mi++)
#pragma unroll
        for (int ni = 0; ni < 8; ni++) {
            int r0 = m0 + wm * 32 + mi * 16 + g;
            int cc = colOff + nblk + wn * 64 + ni * 8 + 2 * q;
            float v0 = acc[mi][ni][0], v1 = acc[mi][ni][1];
            float v2 = acc[mi][ni][2], v3 = acc[mi][ni][3];
            if (EPI == 1) {
                v0 = fmaxf(v0, 0.f); v1 = fmaxf(v1, 0.f);
                v2 = fmaxf(v2, 0.f); v3 = fmaxf(v3, 0.f);
                __nv_bfloat16 h0, l0, h1, l1;
                split1(v0, h0, l0); split1(v1, h1, l1);
                *(__nv_bfloat162*)(Ch + (size_t)r0 * ldC + cc) = __halves2bfloat162(h0, h1);
                *(__nv_bfloat162*)(Cl + (size_t)r0 * ldC + cc) = __halves2bfloat162(l0, l1);
                split1(v2, h0, l0); split1(v3, h1, l1);
                *(__nv_bfloat162*)(Ch + (size_t)(r0 + 8) * ldC + cc) = __halves2bfloat162(h0, h1);
                *(__nv_bfloat162*)(Cl + (size_t)(r0 + 8) * ldC + cc) = __halves2bfloat162(l0, l1);
            } else {
                *(float2*)(C + (size_t)r0 * ldC + cc) = make_float2(v0, v1);
                *(float2*)(C + (size_t)(r0 + 8) * ldC + cc) = make_float2(v2, v3);
            }
        }
}

// ---------------- LayerNorm + ReLU on f1, write split into cat cols [256,512) ----------------
__global__ void k_ln(const float* __restrict__ gamma, const float* __restrict__ beta) {
    int warp = (blockIdx.x * blockDim.x + threadIdx.x) >> 5;
    int lane = threadIdx.x & 31;
    if (warp >= NP) return;
    const float* row = g_f1 + (size_t)warp * H4;
    float4 v0 = ((const float4*)row)[lane];
    float4 v1 = ((const float4*)row)[lane + 32];
    float s = v0.x + v0.y + v0.z + v0.w + v1.x + v1.y + v1.z + v1.w;
    float ss = v0.x * v0.x + v0.y * v0.y + v0.z * v0.z + v0.w * v0.w +
               v1.x * v1.x + v1.y * v1.y + v1.z * v1.z + v1.w * v1.w;
#pragma unroll
    for (int o = 16; o > 0; o >>= 1) {
        s += __shfl_xor_sync(0xffffffffu, s, o);
        ss += __shfl_xor_sync(0xffffffffu, ss, o);
    }
    float mean = s * (1.f / 256.f);
    float var = ss * (1.f / 256.f) - mean * mean;
    float rstd = rsqrtf(var + 1e-5f);
    float4 g0 = ((const float4*)gamma)[lane], g1 = ((const float4*)gamma)[lane + 32];
    float4 b0 = ((const float4*)beta)[lane], b1 = ((const float4*)beta)[lane + 32];
    v0.x = fmaxf((v0.x - mean) * rstd * g0.x + b0.x, 0.f);
    v0.y = fmaxf((v0.y - mean) * rstd * g0.y + b0.y, 0.f);
    v0.z = fmaxf((v0.z - mean) * rstd * g0.z + b0.z, 0.f);
    v0.w = fmaxf((v0.w - mean) * rstd * g0.w + b0.w, 0.f);
    v1.x = fmaxf((v1.x - mean) * rstd * g1.x + b1.x, 0.f);
    v1.y = fmaxf((v1.y - mean) * rstd * g1.y + b1.y, 0.f);
    v1.z = fmaxf((v1.z - mean) * rstd * g1.z + b1.z, 0.f);
    v1.w = fmaxf((v1.w - mean) * rstd * g1.w + b1.w, 0.f);
    uint32_t* ph = (uint32_t*)(g_ch + (size_t)warp * CAT + H4);
    uint32_t* pl = (uint32_t*)(g_cl + (size_t)warp * CAT + H4);
    uint32_t h2[2], l2[2];
    split4(v0, h2, l2);
    ph[lane * 2] = h2[0]; ph[lane * 2 + 1] = h2[1];
    pl[lane * 2] = l2[0]; pl[lane * 2 + 1] = l2[1];
    split4(v1, h2, l2);
    ph[64 + lane * 2] = h2[0]; ph[64 + lane * 2 + 1] = h2[1];
    pl[64 + lane * 2] = l2[0]; pl[64 + lane * 2 + 1] = l2[1];
}

// ---------------- readout normalize ----------------
__global__ void k_norm(float* __restrict__ out) {
    int b = blockIdx.x;
    int t = threadIdx.x;  // 128 threads
    float v = g_readout[b * OUTD + t];
    float ss = v * v;
#pragma unroll
    for (int o = 16; o > 0; o >>= 1) ss += __shfl_xor_sync(0xffffffffu, ss, o);
    __shared__ float sw[4];
    if ((t & 31) == 0) sw[t >> 5] = ss;
    __syncthreads();
    float tot = sw[0] + sw[1] + sw[2] + sw[3];
    float norm = fmaxf(sqrtf(tot), 1e-12f);
    out[b * OUTD + t] = v / norm;
}

// ---------------- launch ----------------
extern "C" void kernel_launch(void* const* d_in, const int* in_sizes, int n_in,
                              void* d_out, int out_size) {
    const float* x    = (const float*)d_in[0];
    const float* w    = (const float*)d_in[1];
    const float* W1   = (const float*)d_in[2];
    const float* fc1W = (const float*)d_in[3];
    const float* gam  = (const float*)d_in[4];
    const float* bet  = (const float*)d_in[5];
    const float* W2   = (const float*)d_in[6];
    const float* W3   = (const float*)d_in[7];
    const int*   src  = (const int*)d_in[8];
    const int*   dst  = (const int*)d_in[9];
    const int*   gid  = (const int*)d_in[10];
    float* out = (float*)d_out;

    float *p_f1, *p_y2, *p_y3;
    __nv_bfloat16 *p_bh, *p_bl, *p_xh, *p_xl, *p_a1h, *p_a1l, *p_ch, *p_cl, *p_x2h, *p_x2l;
    cudaGetSymbolAddress((void**)&p_f1, g_f1);
    cudaGetSymbolAddress((void**)&p_y2, g_y2);
    cudaGetSymbolAddress((void**)&p_y3, g_y3);
    cudaGetSymbolAddress((void**)&p_bh, g_bh);
    cudaGetSymbolAddress((void**)&p_bl, g_bl);
    cudaGetSymbolAddress((void**)&p_xh, g_xh);
    cudaGetSymbolAddress((void**)&p_xl, g_xl);
    cudaGetSymbolAddress((void**)&p_a1h, g_a1h);
    cudaGetSymbolAddress((void**)&p_a1l, g_a1l);
    cudaGetSymbolAddress((void**)&p_ch, g_ch);
    cudaGetSymbolAddress((void**)&p_cl, g_cl);
    cudaGetSymbolAddress((void**)&p_x2h, g_x2h);
    cudaGetSymbolAddress((void**)&p_x2l, g_x2l);

    const int SMEM = 81920;
    cudaFuncSetAttribute(k_mma<128, 1>, cudaFuncAttributeMaxDynamicSharedMemorySize, SMEM);
    cudaFuncSetAttribute(k_mma<128, 0>, cudaFuncAttributeMaxDynamicSharedMemorySize, SMEM);
    cudaFuncSetAttribute(k_mma<512, 0>, cudaFuncAttributeMaxDynamicSharedMemorySize, SMEM);
    cudaFuncSetAttribute(k_mma<256, 0>, cudaFuncAttributeMaxDynamicSharedMemorySize, SMEM);

    const int TB = 256;
    // graph preprocessing
    k_zero<<<(NN + TB - 1) / TB, TB>>>();
    k_deg<<<(NE + TB - 1) / TB, TB>>>(src, dst);
    k_scan_a<<<40, 1024>>>();
    k_scan_b<<<1, 32>>>();
    k_scan_c<<<40, 1024>>>();
    k_place<<<(NE + TB - 1) / TB, TB>>>(src, dst, w);
    // weight + x split
    k_convB_all<<<(229376 + TB - 1) / TB, TB>>>(W1, fc1W, W2, W3);
    k_convA<<<(NP * IND + TB - 1) / TB, TB>>>(x);

    const int AGG_BLK = (NP * 32 + TB - 1) / TB;
    const int GX = NP / 128;  // 313

    // layer 1: agg(x) -> split planes, GEMM 128->256 relu+split into cat[:,0:256)
    k_agg<IND, 0><<<AGG_BLK, TB>>>(x, p_a1h, p_a1l, nullptr);
    k_mma<128, 1><<<dim3(GX, 2), TB, SMEM>>>(p_a1h, p_a1l, p_bh + 0, p_bl + 0,
                                             nullptr, p_ch, p_cl, CAT, 0);
    // fc1: GEMM raw fp32 -> f1, then LN+relu+split into cat[:,256:512)
    k_mma<128, 0><<<dim3(GX, 2), TB, SMEM>>>(p_xh, p_xl, p_bh + 32768, p_bl + 32768,
                                             p_f1, nullptr, nullptr, H4, 0);
    k_ln<<<AGG_BLK, TB>>>(gam, bet);
    // layer 2: GEMM 512->256 raw, agg + relu -> split planes
    k_mma<512, 0><<<dim3(GX, 2), TB, SMEM>>>(p_ch, p_cl, p_bh + 65536, p_bl + 65536,
                                             p_y2, nullptr, nullptr, H4, 0);
    k_agg<H4, 1><<<AGG_BLK, TB>>>(p_y2, p_x2h, p_x2l, nullptr);
    // layer 3: GEMM 256->128 raw, agg + relu + readout
    k_mma<256, 0><<<dim3(GX, 1), TB, SMEM>>>(p_x2h, p_x2l, p_bh + 196608, p_bl + 196608,
                                             p_y3, nullptr, nullptr, OUTD, 0);
    k_agg<OUTD, 2><<<AGG_BLK, TB>>>(p_y3, nullptr, nullptr, gid);
    // final L2 normalize
    k_norm<<<NG, OUTD>>>(out);
}

// round 6
// speedup vs baseline: 1.2642x; 1.2642x over previous
#include <cuda_runtime.h>
#include <cuda_fp16.h>
#include <cstdint>

#define NN 40000
#define NP 40064   // 313 * 128, padded row count
#define NE 320000
#define NG 64
#define IND 128
#define H4 256
#define OUTD 128
#define CAT 512

// ---------------- scratch (device globals; no allocation allowed) ----------------
__device__ int   g_outcnt[NN];
__device__ int   g_incnt[NN];
__device__ int   g_cursor[NN];
__device__ int   g_rowptr[NN + 1];
__device__ int   g_bsum[64];
__device__ float g_outinv[NN];
__device__ float g_ininv[NN];
__device__ int   g_es[NE];
__device__ float g_ec[NE];
__device__ float g_f1[NP * H4];
__device__ float g_y2[NP * H4];
__device__ float g_y3[NP * OUTD];
__device__ float g_readout[NG * OUTD];
// single-plane fp16 activations (A operands of GEMMs), padded to NP rows
__device__ __half g_xh[NP * IND];    // x as fp16
__device__ __half g_a1[NP * IND];    // agg1
__device__ __half g_c[NP * CAT];     // concat [x1 | f1]
__device__ __half g_x2[NP * H4];     // x2
// weights split to fp16 hi/lo, transposed to [N][K]
// layout: W1 @0 (32768), fc1 @32768 (32768), W2 @65536 (131072), W3 @196608 (32768)
__device__ __half g_bh[229376];
__device__ __half g_bl[229376];

// ---------------- helpers ----------------
__device__ __forceinline__ uint32_t smem_u32(const void* p) {
    uint32_t a;
    asm("{ .reg .u64 t; cvta.to.shared.u64 t, %1; cvt.u32.u64 %0, t; }" : "=r"(a) : "l"(p));
    return a;
}
__device__ __forceinline__ void cpa16(uint32_t dst, const void* src) {
    asm volatile("cp.async.cg.shared.global [%0], [%1], 16;" :: "r"(dst), "l"(src) : "memory");
}
__device__ __forceinline__ void cpa_commit() {
    asm volatile("cp.async.commit_group;" ::: "memory");
}
__device__ __forceinline__ void cpa_wait0() {
    asm volatile("cp.async.wait_group 0;" ::: "memory");
}
#define MMA16816(d, a, b)                                                     \
    asm volatile(                                                             \
        "mma.sync.aligned.m16n8k16.row.col.f32.f16.f16.f32 "                  \
        "{%0,%1,%2,%3}, {%4,%5,%6,%7}, {%8,%9}, {%0,%1,%2,%3};"               \
        : "+f"((d)[0]), "+f"((d)[1]), "+f"((d)[2]), "+f"((d)[3])              \
        : "r"((a)[0]), "r"((a)[1]), "r"((a)[2]), "r"((a)[3]),                 \
          "r"((b)[0]), "r"((b)[1]))
#define LDSM4(R, addr)                                                        \
    asm volatile("ldmatrix.sync.aligned.m8n8.x4.shared.b16 {%0,%1,%2,%3}, [%4];" \
        : "=r"((R)[0]), "=r"((R)[1]), "=r"((R)[2]), "=r"((R)[3]) : "r"(addr))

__device__ __forceinline__ void hsplit(float v, __half& h, __half& l) {
    h = __float2half_rn(v);
    l = __float2half_rn(v - __half2float(h));
}

// ---------------- setup kernels ----------------
__global__ void k_zero() {
    int i = blockIdx.x * blockDim.x + threadIdx.x;
    if (i < NN) { g_outcnt[i] = 0; g_incnt[i] = 0; g_cursor[i] = 0; }
    if (i < NG * OUTD) g_readout[i] = 0.f;
}

__global__ void k_deg(const int* __restrict__ src, const int* __restrict__ dst) {
    int e = blockIdx.x * blockDim.x + threadIdx.x;
    if (e < NE) {
        atomicAdd(&g_outcnt[src[e]], 1);
        atomicAdd(&g_incnt[dst[e]], 1);
    }
}

// per-block scan (+ merged inv computation)
__global__ void k_scan_a() {
    __shared__ int sh[1024];
    int b = blockIdx.x, t = threadIdx.x;
    int idx = b * 1024 + t;
    int v = (idx < NN) ? g_incnt[idx] : 0;
    if (idx < NN) {
        g_ininv[idx]  = rsqrtf((float)max(v, 1));
        g_outinv[idx] = rsqrtf((float)max(g_outcnt[idx], 1));
    }
    sh[t] = v;
    __syncthreads();
#pragma unroll
    for (int off = 1; off < 1024; off <<= 1) {
        int u = (t >= off) ? sh[t - off] : 0;
        __syncthreads();
        sh[t] += u;
        __syncthreads();
    }
    int incl = sh[t];
    if (idx <= NN) g_rowptr[idx] = incl - v;
    if (t == 1023) g_bsum[b] = incl;
}
// add block-prefix offsets (inline ≤40-element prefix; replaces scan_b+scan_c)
__global__ void k_scan_c() {
    __shared__ int pre;
    int b = blockIdx.x, t = threadIdx.x;
    if (t == 0) {
        int s = 0;
        for (int i = 0; i < b; i++) s += g_bsum[i];
        pre = s;
    }
    __syncthreads();
    int idx = b * 1024 + t;
    if (idx <= NN) g_rowptr[idx] += pre;
}

__global__ void k_place(const int* __restrict__ src, const int* __restrict__ dst,
                        const float* __restrict__ w) {
    int e = blockIdx.x * blockDim.x + threadIdx.x;
    if (e >= NE) return;
    float4 ww = *(const float4*)(w + 4 * e);
    float m = fmaxf(fmaxf(ww.x, ww.y), fmaxf(ww.z, ww.w));
    int d = dst[e];
    int s = src[e];
    int pos = g_rowptr[d] + atomicAdd(&g_cursor[d], 1);
    g_es[pos] = s;
    g_ec[pos] = m * g_outinv[s];
}

// all 4 weights: fp32 [K][N] -> fp16 hi/lo [N][K], one kernel
__global__ void k_convB_all(const float* __restrict__ W1, const float* __restrict__ F1,
                            const float* __restrict__ W2, const float* __restrict__ W3) {
    int idx = blockIdx.x * blockDim.x + threadIdx.x;
    if (idx >= 229376) return;
    const float* W; int K, N, base;
    if (idx < 32768)       { W = W1; K = 128; N = 256; base = 0; }
    else if (idx < 65536)  { W = F1; K = 128; N = 256; base = 32768; }
    else if (idx < 196608) { W = W2; K = 512; N = 256; base = 65536; }
    else                   { W = W3; K = 256; N = 128; base = 196608; }
    int li = idx - base;
    int k = li % K, n = li / K;
    float v = W[k * N + n];
    __half h, l;
    hsplit(v, h, l);
    g_bh[idx] = h;
    g_bl[idx] = l;
}

// x -> fp16 plane (pads zeroed)
__global__ void k_convA(const float* __restrict__ x) {
    int idx = blockIdx.x * blockDim.x + threadIdx.x;
    if (idx >= NP * IND) return;
    float v = (idx < NN * IND) ? x[idx] : 0.f;
    g_xh[idx] = __float2half_rn(v);
}

// ---------------- aggregation: one warp per dst node ----------------
// MODE 0: fp16 out (no relu); MODE 1: relu + fp16 out; MODE 2: relu + readout atomics
template <int D, int MODE>
__global__ void k_agg(const float* __restrict__ in, __half* __restrict__ oh,
                      const int* __restrict__ gid) {
    int warp = (blockIdx.x * blockDim.x + threadIdx.x) >> 5;
    int lane = threadIdx.x & 31;
    if (warp >= NP) return;
    constexpr int V = D / 128;
    if (warp >= NN) {  // pad rows: zero plane
        if (MODE != 2) {
            uint32_t* ph = (uint32_t*)(oh + (size_t)warp * D);
#pragma unroll
            for (int v = 0; v < V; v++) {
                ph[v * 64 + lane * 2] = 0;
                ph[v * 64 + lane * 2 + 1] = 0;
            }
        }
        return;
    }
    int beg = g_rowptr[warp];
    int end = g_rowptr[warp + 1];
    float4 acc[V];
#pragma unroll
    for (int v = 0; v < V; v++) acc[v] = make_float4(0.f, 0.f, 0.f, 0.f);
    int e = beg;
    for (; e + 1 < end; e += 2) {  // 2-way unroll for MLP
        int s0 = g_es[e], s1 = g_es[e + 1];
        float c0 = g_ec[e], c1 = g_ec[e + 1];
        const float4* p0 = (const float4*)(in + (size_t)s0 * D) + lane;
        const float4* p1 = (const float4*)(in + (size_t)s1 * D) + lane;
#pragma unroll
        for (int v = 0; v < V; v++) {
            float4 t0 = p0[v * 32];
            float4 t1 = p1[v * 32];
            acc[v].x = fmaf(c0, t0.x, fmaf(c1, t1.x, acc[v].x));
            acc[v].y = fmaf(c0, t0.y, fmaf(c1, t1.y, acc[v].y));
            acc[v].z = fmaf(c0, t0.z, fmaf(c1, t1.z, acc[v].z));
            acc[v].w = fmaf(c0, t0.w, fmaf(c1, t1.w, acc[v].w));
        }
    }
    if (e < end) {
        int s = g_es[e];
        float c = g_ec[e];
        const float4* p = (const float4*)(in + (size_t)s * D) + lane;
#pragma unroll
        for (int v = 0; v < V; v++) {
            float4 t = p[v * 32];
            acc[v].x = fmaf(c, t.x, acc[v].x);
            acc[v].y = fmaf(c, t.y, acc[v].y);
            acc[v].z = fmaf(c, t.z, acc[v].z);
            acc[v].w = fmaf(c, t.w, acc[v].w);
        }
    }
    float inv = g_ininv[warp];
#pragma unroll
    for (int v = 0; v < V; v++) {
        acc[v].x *= inv; acc[v].y *= inv; acc[v].z *= inv; acc[v].w *= inv;
        if (MODE >= 1) {
            acc[v].x = fmaxf(acc[v].x, 0.f);
            acc[v].y = fmaxf(acc[v].y, 0.f);
            acc[v].z = fmaxf(acc[v].z, 0.f);
            acc[v].w = fmaxf(acc[v].w, 0.f);
        }
    }
    if (MODE == 2) {
        int g = gid[warp];
        float* r = g_readout + g * OUTD + lane * 4;
        atomicAdd(r + 0, acc[0].x);
        atomicAdd(r + 1, acc[0].y);
        atomicAdd(r + 2, acc[0].z);
        atomicAdd(r + 3, acc[0].w);
    } else {
        uint32_t* ph = (uint32_t*)(oh + (size_t)warp * D);
#pragma unroll
        for (int v = 0; v < V; v++) {
            __half2 a = __floats2half2_rn(acc[v].x, acc[v].y);
            __half2 b = __floats2half2_rn(acc[v].z, acc[v].w);
            ph[v * 64 + lane * 2] = *(uint32_t*)&a;
            ph[v * 64 + lane * 2 + 1] = *(uint32_t*)&b;
        }
    }
}

// ---------------- fp16 2-term mma.sync GEMM ----------------
// C[M,N] = A@(Bh+Bl), A single fp16 plane, B split fp16 hi/lo, fp32 accum.
// Block tile 128x128, BK=32 k-positions per stage, 2-stage cp.async pipeline.
// smem rows padded to 80B -> conflict-free ldmatrix.
// EPI: 0 = raw fp32 out, 1 = relu + fp16 out
template <int K, int EPI>
__global__ __launch_bounds__(256, 2) void k_mma(
    const __half* __restrict__ Ah,
    const __half* __restrict__ Bh, const __half* __restrict__ Bl,
    float* __restrict__ C, __half* __restrict__ Ch, int ldC, int colOff) {
    extern __shared__ __align__(16) uint8_t smem[];
    constexpr int NC = K / 32;
    constexpr uint32_t AH_ = 0, BH_ = 10240, BL_ = 20480, STG = 30720;
    const int tid = threadIdx.x;
    const int wid = tid >> 5, lane = tid & 31;
    const int wm = wid & 3, wn = wid >> 2;
    const int m0 = blockIdx.x * 128;
    const int nblk = blockIdx.y * 128;
    const uint32_t sb = smem_u32(smem);

    float acc[2][8][4];
#pragma unroll
    for (int mi = 0; mi < 2; mi++)
#pragma unroll
        for (int ni = 0; ni < 8; ni++)
#pragma unroll
            for (int r = 0; r < 4; r++) acc[mi][ni][r] = 0.f;

    // loaders: A 2 chunks/thread, B 4 chunks/thread (64B rows per stage)
    const int arow = tid >> 1, ah_ = tid & 1;
    const __half* aS = Ah + (size_t)(m0 + arow) * K + ah_ * 16;
    const uint32_t aD = AH_ + (uint32_t)arow * 80 + ah_ * 32;
    const int brow = tid & 127, bpl = tid >> 7;
    const __half* bS = (bpl ? Bl : Bh) + (size_t)(nblk + brow) * K;
    const uint32_t bD = (bpl ? BL_ : BH_) + (uint32_t)brow * 80;

    // fragment base offsets (ldmatrix thread mapping)
    const uint32_t aoff = AH_ + (uint32_t)(wm * 32 + (lane & 7) + ((lane >> 3) & 1) * 8) * 80 +
                          (lane >> 4) * 16;
    const uint32_t boff = BH_ + (uint32_t)(wn * 64 + ((lane >> 4) & 1) * 8 + (lane & 7)) * 80 +
                          ((lane >> 3) & 1) * 16;

    // prologue: stage 0
    {
        cpa16(sb + aD, aS);
        cpa16(sb + aD + 16, aS + 8);
#pragma unroll
        for (int j = 0; j < 4; j++) cpa16(sb + bD + j * 16, bS + j * 8);
        cpa_commit();
    }

    for (int c = 0; c < NC; c++) {
        cpa_wait0();
        __syncthreads();
        if (c + 1 < NC) {
            uint32_t st = sb + ((c + 1) & 1) * STG;
            const __half* ap = aS + (c + 1) * 32;
            const __half* bp = bS + (c + 1) * 32;
            cpa16(st + aD, ap);
            cpa16(st + aD + 16, ap + 8);
#pragma unroll
            for (int j = 0; j < 4; j++) cpa16(st + bD + j * 16, bp + j * 8);
            cpa_commit();
        }
        uint32_t st = sb + (c & 1) * STG;
#pragma unroll
        for (int kk = 0; kk < 2; kk++) {
            const uint32_t ko = kk * 32;
            uint32_t af[2][4], bf[8][2];
#pragma unroll
            for (int mi = 0; mi < 2; mi++) LDSM4(af[mi], st + aoff + mi * 1280 + ko);
#pragma unroll
            for (int p = 0; p < 4; p++) {
                uint32_t r4[4];
                LDSM4(r4, st + boff + p * 1280 + ko);
                bf[2 * p][0] = r4[0]; bf[2 * p][1] = r4[1];
                bf[2 * p + 1][0] = r4[2]; bf[2 * p + 1][1] = r4[3];
            }
#pragma unroll
            for (int mi = 0; mi < 2; mi++)
#pragma unroll
                for (int ni = 0; ni < 8; ni++) MMA16816(acc[mi][ni], af[mi], bf[ni]);
#pragma unroll
            for (int p = 0; p < 4; p++) {
                uint32_t r4[4];
                LDSM4(r4, st + boff + (BL_ - BH_) + p * 1280 + ko);
                bf[2 * p][0] = r4[0]; bf[2 * p][1] = r4[1];
                bf[2 * p + 1][0] = r4[2]; bf[2 * p + 1][1] = r4[3];
            }
#pragma unroll
            for (int mi = 0; mi < 2; mi++)
#pragma unroll
                for (int ni = 0; ni < 8; ni++) MMA16816(acc[mi][ni], af[mi], bf[ni]);
        }
        __syncthreads();
    }

    // epilogue (buffers NP-padded: no row guards)
    const int g = lane >> 2, q = lane & 3;
#pragma unroll
    for (int mi = 0; mi < 2; mi++)
#pragma unroll
        for (int ni = 0; ni < 8; ni++) {
            int r0 = m0 + wm * 32 + mi * 16 + g;
            int cc = colOff + nblk + wn * 64 + ni * 8 + 2 * q;
            float v0 = acc[mi][ni][0], v1 = acc[mi][ni][1];
            float v2 = acc[mi][ni][2], v3 = acc[mi][ni][3];
            if (EPI == 1) {
                v0 = fmaxf(v0, 0.f); v1 = fmaxf(v1, 0.f);
                v2 = fmaxf(v2, 0.f); v3 = fmaxf(v3, 0.f);
                __half2 a = __floats2half2_rn(v0, v1);
                __half2 b = __floats2half2_rn(v2, v3);
                *(__half2*)(Ch + (size_t)r0 * ldC + cc) = a;
                *(__half2*)(Ch + (size_t)(r0 + 8) * ldC + cc) = b;
            } else {
                *(float2*)(C + (size_t)r0 * ldC + cc) = make_float2(v0, v1);
                *(float2*)(C + (size_t)(r0 + 8) * ldC + cc) = make_float2(v2, v3);
            }
        }
}

// ---------------- LayerNorm + ReLU on f1, write fp16 into cat cols [256,512) ----------------
__global__ void k_ln(const float* __restrict__ gamma, const float* __restrict__ beta) {
    int warp = (blockIdx.x * blockDim.x + threadIdx.x) >> 5;
    int lane = threadIdx.x & 31;
    if (warp >= NP) return;
    const float* row = g_f1 + (size_t)warp * H4;
    float4 v0 = ((const float4*)row)[lane];
    float4 v1 = ((const float4*)row)[lane + 32];
    float s = v0.x + v0.y + v0.z + v0.w + v1.x + v1.y + v1.z + v1.w;
    float ss = v0.x * v0.x + v0.y * v0.y + v0.z * v0.z + v0.w * v0.w +
               v1.x * v1.x + v1.y * v1.y + v1.z * v1.z + v1.w * v1.w;
#pragma unroll
    for (int o = 16; o > 0; o >>= 1) {
        s += __shfl_xor_sync(0xffffffffu, s, o);
        ss += __shfl_xor_sync(0xffffffffu, ss, o);
    }
    float mean = s * (1.f / 256.f);
    float var = ss * (1.f / 256.f) - mean * mean;
    float rstd = rsqrtf(var + 1e-5f);
    float4 g0 = ((const float4*)gamma)[lane], g1 = ((const float4*)gamma)[lane + 32];
    float4 b0 = ((const float4*)beta)[lane], b1 = ((const float4*)beta)[lane + 32];
    v0.x = fmaxf((v0.x - mean) * rstd * g0.x + b0.x, 0.f);
    v0.y = fmaxf((v0.y - mean) * rstd * g0.y + b0.y, 0.f);
    v0.z = fmaxf((v0.z - mean) * rstd * g0.z + b0.z, 0.f);
    v0.w = fmaxf((v0.w - mean) * rstd * g0.w + b0.w, 0.f);
    v1.x = fmaxf((v1.x - mean) * rstd * g1.x + b1.x, 0.f);
    v1.y = fmaxf((v1.y - mean) * rstd * g1.y + b1.y, 0.f);
    v1.z = fmaxf((v1.z - mean) * rstd * g1.z + b1.z, 0.f);
    v1.w = fmaxf((v1.w - mean) * rstd * g1.w + b1.w, 0.f);
    uint32_t* ph = (uint32_t*)(g_c + (size_t)warp * CAT + H4);
    __half2 a = __floats2half2_rn(v0.x, v0.y), b = __floats2half2_rn(v0.z, v0.w);
    ph[lane * 2] = *(uint32_t*)&a;
    ph[lane * 2 + 1] = *(uint32_t*)&b;
    a = __floats2half2_rn(v1.x, v1.y); b = __floats2half2_rn(v1.z, v1.w);
    ph[64 + lane * 2] = *(uint32_t*)&a;
    ph[64 + lane * 2 + 1] = *(uint32_t*)&b;
}

// ---------------- readout normalize ----------------
__global__ void k_norm(float* __restrict__ out) {
    int b = blockIdx.x;
    int t = threadIdx.x;  // 128 threads
    float v = g_readout[b * OUTD + t];
    float ss = v * v;
#pragma unroll
    for (int o = 16; o > 0; o >>= 1) ss += __shfl_xor_sync(0xffffffffu, ss, o);
    __shared__ float sw[4];
    if ((t & 31) == 0) sw[t >> 5] = ss;
    __syncthreads();
    float tot = sw[0] + sw[1] + sw[2] + sw[3];
    float norm = fmaxf(sqrtf(tot), 1e-12f);
    out[b * OUTD + t] = v / norm;
}

// ---------------- launch ----------------
extern "C" void kernel_launch(void* const* d_in, const int* in_sizes, int n_in,
                              void* d_out, int out_size) {
    const float* x    = (const float*)d_in[0];
    const float* w    = (const float*)d_in[1];
    const float* W1   = (const float*)d_in[2];
    const float* fc1W = (const float*)d_in[3];
    const float* gam  = (const float*)d_in[4];
    const float* bet  = (const float*)d_in[5];
    const float* W2   = (const float*)d_in[6];
    const float* W3   = (const float*)d_in[7];
    const int*   src  = (const int*)d_in[8];
    const int*   dst  = (const int*)d_in[9];
    const int*   gid  = (const int*)d_in[10];
    float* out = (float*)d_out;

    float *p_f1, *p_y2, *p_y3;
    __half *p_bh, *p_bl, *p_xh, *p_a1, *p_c, *p_x2;
    cudaGetSymbolAddress((void**)&p_f1, g_f1);
    cudaGetSymbolAddress((void**)&p_y2, g_y2);
    cudaGetSymbolAddress((void**)&p_y3, g_y3);
    cudaGetSymbolAddress((void**)&p_bh, g_bh);
    cudaGetSymbolAddress((void**)&p_bl, g_bl);
    cudaGetSymbolAddress((void**)&p_xh, g_xh);
    cudaGetSymbolAddress((void**)&p_a1, g_a1);
    cudaGetSymbolAddress((void**)&p_c, g_c);
    cudaGetSymbolAddress((void**)&p_x2, g_x2);

    const int SMEM = 61440;
    cudaFuncSetAttribute(k_mma<128, 1>, cudaFuncAttributeMaxDynamicSharedMemorySize, SMEM);
    cudaFuncSetAttribute(k_mma<128, 0>, cudaFuncAttributeMaxDynamicSharedMemorySize, SMEM);
    cudaFuncSetAttribute(k_mma<512, 0>, cudaFuncAttributeMaxDynamicSharedMemorySize, SMEM);
    cudaFuncSetAttribute(k_mma<256, 0>, cudaFuncAttributeMaxDynamicSharedMemorySize, SMEM);

    const int TB = 256;
    // graph preprocessing
    k_zero<<<(NN + TB - 1) / TB, TB>>>();
    k_deg<<<(NE + TB - 1) / TB, TB>>>(src, dst);
    k_scan_a<<<40, 1024>>>();
    k_scan_c<<<40, 1024>>>();
    k_place<<<(NE + TB - 1) / TB, TB>>>(src, dst, w);
    // weight + x conversion
    k_convB_all<<<(229376 + TB - 1) / TB, TB>>>(W1, fc1W, W2, W3);
    k_convA<<<(NP * IND + TB - 1) / TB, TB>>>(x);

    const int AGG_BLK = (NP * 32 + TB - 1) / TB;
    const int GX = NP / 128;  // 313

    // layer 1: agg(x) -> fp16 plane, GEMM 128->256 relu+fp16 into cat[:,0:256)
    k_agg<IND, 0><<<AGG_BLK, TB>>>(x, p_a1, nullptr);
    k_mma<128, 1><<<dim3(GX, 2), TB, SMEM>>>(p_a1, p_bh + 0, p_bl + 0,
                                             nullptr, p_c, CAT, 0);
    // fc1: GEMM raw fp32 -> f1, then LN+relu+fp16 into cat[:,256:512)
    k_mma<128, 0><<<dim3(GX, 2), TB, SMEM>>>(p_xh, p_bh + 32768, p_bl + 32768,
                                             p_f1, nullptr, H4, 0);
    k_ln<<<AGG_BLK, TB>>>(gam, bet);
    // layer 2: GEMM 512->256 raw, agg + relu -> fp16 plane
    k_mma<512, 0><<<dim3(GX, 2), TB, SMEM>>>(p_c, p_bh + 65536, p_bl + 65536,
                                             p_y2, nullptr, H4, 0);
    k_agg<H4, 1><<<AGG_BLK, TB>>>(p_y2, p_x2, nullptr);
    // layer 3: GEMM 256->128 raw, agg + relu + readout
    k_mma<256, 0><<<dim3(GX, 1), TB, SMEM>>>(p_x2, p_bh + 196608, p_bl + 196608,
                                             p_y3, nullptr, OUTD, 0);
    k_agg<OUTD, 2><<<AGG_BLK, TB>>>(p_y3, nullptr, gid);
    // final L2 normalize
    k_norm<<<NG, OUTD>>>(out);
}